// round 1
// baseline (speedup 1.0000x reference)
#include <cuda_runtime.h>

// HopfieldNetwork: B=8 samples, N=4096 neurons, ITERS=10 async sweeps.
// Algorithm: maintain z = W.y incrementally (fp64 for sign fidelity).
//   Step t flips neuron i=perm[t] iff sign(z[i]) != y[i]; a flip does
//   z += (s - y_old) * W[i,:]  (W symmetric, zero diag).
// Non-flip steps are detected 512-wide via a shared sign(z) mirror.

constexpr int NN  = 4096;
constexpr int TPB = 512;          // threads per sequential block = scan window
constexpr int ZPT = NN / TPB;     // 8 fp64 z elements per thread (registers)

__device__ double g_z[8 * NN];    // initial fields, written by gemv_init

// ---------------------------------------------------------------------------
// Kernel 1: z0[b][row] = sum_k W[row][k] * x[b][k], fp64 accumulation.
// One block per row; each W element feeds all B samples.
// ---------------------------------------------------------------------------
__global__ void __launch_bounds__(256) gemv_init(const float* __restrict__ W,
                                                 const float* __restrict__ x,
                                                 int B)
{
    const int row = blockIdx.x;
    const int tid = threadIdx.x;

    double acc[8];
#pragma unroll
    for (int b = 0; b < 8; b++) acc[b] = 0.0;

    const float* wrow = W + (size_t)row * NN;
    for (int c = tid; c < NN; c += 256) {
        float w = wrow[c];
#pragma unroll
        for (int b = 0; b < 8; b++) {
            if (b < B) {
                float xv = x[b * NN + c];
                acc[b] = fma((double)w, (double)xv, acc[b]);
            }
        }
    }

    // warp reduce each of the 8 accumulators
#pragma unroll
    for (int b = 0; b < 8; b++) {
#pragma unroll
        for (int off = 16; off > 0; off >>= 1)
            acc[b] += __shfl_down_sync(0xffffffffu, acc[b], off);
    }

    __shared__ double red[8][8];   // [warp][b]
    const int warp = tid >> 5, lane = tid & 31;
    if (lane == 0) {
#pragma unroll
        for (int b = 0; b < 8; b++) red[warp][b] = acc[b];
    }
    __syncthreads();
    if (tid < 8) {                  // tid plays the role of b
        double s = 0.0;
#pragma unroll
        for (int w2 = 0; w2 < 8; w2++) s += red[w2][tid];
        if (tid < B) g_z[tid * NN + row] = s;
    }
}

// ---------------------------------------------------------------------------
// Kernel 2: one block per sample. z lives in fp64 registers (thread t owns
// z[t*8 .. t*8+7]); sign(z) mirror + y live in shared memory for the scan.
// Each window: 512 threads test 512 consecutive perm steps; first flip found
// by ballot + shared atomicMin; axpy the W row; restart after the flip.
// ---------------------------------------------------------------------------
__global__ void __launch_bounds__(TPB) hopfield_seq(
    const float* __restrict__ W,
    const float* __restrict__ x,
    const int*   __restrict__ perms,
    float*       __restrict__ out,
    int iters)
{
    const int b    = blockIdx.x;
    const int tid  = threadIdx.x;
    const int base = tid * ZPT;

    __shared__ __align__(16) signed char sh_y[NN];   // current state (-1/0/+1)
    __shared__ __align__(16) signed char sh_s[NN];   // sign(z) mirror
    __shared__ int   sh_first;
    __shared__ int   sh_fi;
    __shared__ float sh_fd;

    // load my slice of z and publish initial signs / state
    double z[ZPT];
#pragma unroll
    for (int k = 0; k < ZPT; k++) z[k] = g_z[b * NN + base + k];

#pragma unroll
    for (int k = 0; k < ZPT; k++) {
        float xv = x[b * NN + base + k];
        sh_y[base + k] = xv > 0.f ? (signed char)1 : (xv < 0.f ? (signed char)-1 : (signed char)0);
        sh_s[base + k] = z[k] > 0.0 ? (signed char)1 : (z[k] < 0.0 ? (signed char)-1 : (signed char)0);
    }
    if (tid == 0) sh_first = TPB;
    __syncthreads();

    const int  TOTAL = iters * NN;
    const int* pb    = perms + (size_t)b * TOTAL;

    int t = 0;
    while (t < TOTAL) {
        const int step = t + tid;
        int i = 0;
        signed char sv = 0, yv = 0;
        bool flip = false;
        if (step < TOTAL) {
            i  = pb[step];
            sv = sh_s[i];
            yv = sh_y[i];
            flip = (sv != yv);
        }

        // earliest flipping thread in the block
        unsigned ball = __ballot_sync(0xffffffffu, flip);
        if (ball != 0u && (int)(tid & 31) == (__ffs(ball) - 1))
            atomicMin(&sh_first, tid);
        __syncthreads();                       // publish sh_first

        const int first = sh_first;
        if (first != TPB) {
            if (tid == first) {                // winner publishes the flip
                sh_fi = i;
                sh_fd = (float)(sv - yv);      // +-2 (or +-1 in the z==0 corner)
                sh_y[i] = sv;
            }
        }
        __syncthreads();                       // publish flip info; also orders
                                               // sh_first reads vs next window writes
        if (first != TPB) {
            const int   fi = sh_fi;
            const float fd = sh_fd;
            const float4* w4 =
                reinterpret_cast<const float4*>(W + (size_t)fi * NN + base);
            const float4 wa = w4[0];
            const float4 wb = w4[1];
            const float wv[ZPT] = {wa.x, wa.y, wa.z, wa.w,
                                   wb.x, wb.y, wb.z, wb.w};
            unsigned long long pk = 0ull;
#pragma unroll
            for (int k = 0; k < ZPT; k++) {
                z[k] += (double)(fd * wv[k]);  // fd*w exact in fp32, DADD in fp64
                signed char s = z[k] > 0.0 ? (signed char)1
                              : (z[k] < 0.0 ? (signed char)-1 : (signed char)0);
                pk |= ((unsigned long long)(unsigned char)s) << (8 * k);
            }
            *reinterpret_cast<unsigned long long*>(&sh_s[base]) = pk;
            if (tid == 0) sh_first = TPB;
            t += first + 1;                    // resume right after the flip
            __syncthreads();                   // publish sh_s + sh_first reset
        } else {
            t += TPB;                          // whole window stable
        }
    }

    __syncthreads();
#pragma unroll
    for (int k = 0; k < ZPT; k++)
        out[b * NN + base + k] = (float)sh_y[base + k];
}

// ---------------------------------------------------------------------------
extern "C" void kernel_launch(void* const* d_in, const int* in_sizes, int n_in,
                              void* d_out, int out_size)
{
    const float* x     = (const float*)d_in[0];   // [B, N]  bipolar
    const float* W     = (const float*)d_in[1];   // [N, N]  symmetric, zero diag
    const int*   perms = (const int*)  d_in[2];   // [B, ITERS, N]
    float*       out   = (float*)d_out;           // [B, N]

    const int B     = in_sizes[0] / NN;
    const int iters = in_sizes[2] / in_sizes[0];

    gemv_init<<<NN, 256>>>(W, x, B);
    hopfield_seq<<<B, TPB>>>(W, x, perms, out, iters);
}

// round 2
// speedup vs baseline: 1.2593x; 1.2593x over previous
#include <cuda_runtime.h>

// HopfieldNetwork: B=8, N=4096, ITERS=10 async sweeps.
// z = W.y maintained incrementally in fp64 registers (8 per thread).
// Per window: 512 threads test 512 future perm steps against a shared
// sign(z) mirror; first flip found via ballot + 16 warp slots (packed key
// carrying tid|i|sign|y), then a W-row axpy. Signs extracted with integer
// bit tricks (ALU pipe) to keep the fp64 pipe DADD-only.

constexpr int NN  = 4096;
constexpr int TPB = 512;
constexpr int ZPT = NN / TPB;     // 8 doubles per thread

__device__ double g_z[8 * NN];

// enc: -1 -> 0, 0 -> 1, +1 -> 2   (so delta = se - ye directly)
__device__ __forceinline__ int enc_sign(double v) {
    long long b = __double_as_longlong(v);
    if ((b << 1) == 0) return 1;      // +-0.0
    return b > 0 ? 2 : 0;
}

// ---------------------------------------------------------------------------
// Kernel 1: z0[b][row] = W[row] . x[b], fp64 accumulation. One block per row.
// ---------------------------------------------------------------------------
__global__ void __launch_bounds__(256) gemv_init(const float* __restrict__ W,
                                                 const float* __restrict__ x,
                                                 int B)
{
    const int row = blockIdx.x;
    const int tid = threadIdx.x;

    double acc[8];
#pragma unroll
    for (int b = 0; b < 8; b++) acc[b] = 0.0;

    const float* wrow = W + (size_t)row * NN;
    for (int c = tid; c < NN; c += 256) {
        float w = wrow[c];
#pragma unroll
        for (int b = 0; b < 8; b++) {
            if (b < B) {
                float xv = x[b * NN + c];
                acc[b] = fma((double)w, (double)xv, acc[b]);
            }
        }
    }
#pragma unroll
    for (int b = 0; b < 8; b++) {
#pragma unroll
        for (int off = 16; off > 0; off >>= 1)
            acc[b] += __shfl_down_sync(0xffffffffu, acc[b], off);
    }
    __shared__ double red[8][8];
    const int warp = tid >> 5, lane = tid & 31;
    if (lane == 0) {
#pragma unroll
        for (int b = 0; b < 8; b++) red[warp][b] = acc[b];
    }
    __syncthreads();
    if (tid < 8) {
        double s = 0.0;
#pragma unroll
        for (int w2 = 0; w2 < 8; w2++) s += red[w2][tid];
        if (tid < B) g_z[tid * NN + row] = s;
    }
}

// ---------------------------------------------------------------------------
// Kernel 2: one block per sample.
// Key pack: bits[0:2]=enc(y), [2:4]=enc(sign z), [4:16]=i, [16:26]=tid.
// Min key == min tid (tid unique). INT_MAX = no candidate.
// ---------------------------------------------------------------------------
__global__ void __launch_bounds__(TPB) hopfield_seq(
    const float* __restrict__ W,
    const float* __restrict__ x,
    const int*   __restrict__ perms,
    float*       __restrict__ out,
    int iters)
{
    const int b    = blockIdx.x;
    const int tid  = threadIdx.x;
    const int lane = tid & 31;
    const int wid  = tid >> 5;
    const int base = tid * ZPT;

    __shared__ __align__(16) signed char sh_y[NN];   // enc(y)
    __shared__ __align__(16) signed char sh_s[NN];   // enc(sign z)
    __shared__ __align__(16) int sh_slot[2][16];

    double z[ZPT];
#pragma unroll
    for (int k = 0; k < ZPT; k++) z[k] = g_z[b * NN + base + k];

    {
        unsigned long long py = 0ull, ps = 0ull;
#pragma unroll
        for (int k = 0; k < ZPT; k++) {
            float xv = x[b * NN + base + k];
            int ye = xv > 0.f ? 2 : (xv < 0.f ? 0 : 1);
            int se = enc_sign(z[k]);
            py |= ((unsigned long long)(unsigned)ye) << (8 * k);
            ps |= ((unsigned long long)(unsigned)se) << (8 * k);
        }
        *reinterpret_cast<unsigned long long*>(&sh_y[base]) = py;
        *reinterpret_cast<unsigned long long*>(&sh_s[base]) = ps;
    }
    __syncthreads();

    const int  TOTAL = iters * NN;
    const int* pb    = perms + (size_t)b * TOTAL;

    int t = 0;
    int parity = 0;
    while (t < TOTAL) {
        // ---- scan: does step t+tid want to flip? ----
        const int step = t + tid;
        int key = 0x7FFFFFFF;
        if (step < TOTAL) {
            const int i  = __ldg(pb + step);
            const int se = sh_s[i];
            const int ye = sh_y[i];
            if (se != ye)
                key = (tid << 16) | (i << 4) | (se << 2) | ye;
        }
        const unsigned ball = __ballot_sync(0xffffffffu, key != 0x7FFFFFFF);
        if (ball != 0u) {
            if (lane == __ffs(ball) - 1) sh_slot[parity][wid] = key;
        } else if (lane == 0) {
            sh_slot[parity][wid] = 0x7FFFFFFF;
        }
        __syncthreads();                               // barrier 1

        // ---- block-wide min over 16 slots (registers) ----
        int sl[16];
        {
            const int4* s4 = reinterpret_cast<const int4*>(sh_slot[parity]);
            int4 a = s4[0], c = s4[1], d = s4[2], e = s4[3];
            sl[0]=a.x; sl[1]=a.y; sl[2]=a.z;  sl[3]=a.w;
            sl[4]=c.x; sl[5]=c.y; sl[6]=c.z;  sl[7]=c.w;
            sl[8]=d.x; sl[9]=d.y; sl[10]=d.z; sl[11]=d.w;
            sl[12]=e.x; sl[13]=e.y; sl[14]=e.z; sl[15]=e.w;
        }
        int mk = 0x7FFFFFFF;
#pragma unroll
        for (int q = 0; q < 16; q++) mk = min(mk, sl[q]);
        parity ^= 1;

        if (mk == 0x7FFFFFFF) {                        // stable window: 1 barrier
            t += TPB;
            continue;
        }

        const int first = mk >> 16;
        const int fi    = (mk >> 4) & 0xFFF;
        const int se    = (mk >> 2) & 3;
        const int ye    = mk & 3;
        const float fd  = (float)(se - ye);            // +-2 (or +-1 vs 0)

        if (tid == 0) sh_y[fi] = (signed char)se;

        // speculative prefetch of the 2nd candidate's W row into L1
        {
            int mk2 = 0x7FFFFFFF;
#pragma unroll
            for (int q = 0; q < 16; q++) {
                int v = (sl[q] == mk) ? 0x7FFFFFFF : sl[q];
                mk2 = min(mk2, v);
            }
            if (mk2 != 0x7FFFFFFF && (tid & 3) == 0) {
                const int i2 = (mk2 >> 4) & 0xFFF;
                const float* p = W + (size_t)i2 * NN + base;
                asm volatile("prefetch.global.L1 [%0];" :: "l"(p));
            }
        }

        // ---- axpy: z += fd * W[fi], signs via integer ops ----
        {
            const float4* w4 =
                reinterpret_cast<const float4*>(W + (size_t)fi * NN + base);
            const float4 wa = __ldg(w4 + 0);
            const float4 wb = __ldg(w4 + 1);
            const float wv[ZPT] = {wa.x, wa.y, wa.z, wa.w,
                                   wb.x, wb.y, wb.z, wb.w};
            unsigned long long ps = 0ull;
#pragma unroll
            for (int k = 0; k < ZPT; k++) {
                z[k] += (double)(fd * wv[k]);          // fd*w exact in fp32
                ps |= ((unsigned long long)(unsigned)enc_sign(z[k])) << (8 * k);
            }
            *reinterpret_cast<unsigned long long*>(&sh_s[base]) = ps;
        }

        t += first + 1;
        __syncthreads();                               // barrier 2
    }

    __syncthreads();
#pragma unroll
    for (int k = 0; k < ZPT; k++)
        out[b * NN + base + k] = (float)((int)sh_y[base + k] - 1);
}

// ---------------------------------------------------------------------------
extern "C" void kernel_launch(void* const* d_in, const int* in_sizes, int n_in,
                              void* d_out, int out_size)
{
    const float* x     = (const float*)d_in[0];
    const float* W     = (const float*)d_in[1];
    const int*   perms = (const int*)  d_in[2];
    float*       out   = (float*)d_out;

    const int B     = in_sizes[0] / NN;
    const int iters = in_sizes[2] / in_sizes[0];

    gemv_init<<<NN, 256>>>(W, x, B);
    hopfield_seq<<<B, TPB>>>(W, x, perms, out, iters);
}

// round 3
// speedup vs baseline: 1.7094x; 1.3574x over previous
#include <cuda_runtime.h>

// HopfieldNetwork: B=8, N=4096, ITERS=10 asynchronous sweeps.
// z = W.y kept incrementally in fp64 registers (16/thread, TPB=256).
// sh_comb[i] byte: bit1 = (z[i]<0), bit0 = (y[i]<0). flip iff bits differ.
// Window scan: 256 threads test 256 future perm steps (perm index cached in
// registers); earliest flip via warp ballot + 8 slots + min; W-row axpy with
// PRMT-based sign repack; runner-up candidate row prefetched into L1.

constexpr int NN  = 4096;
constexpr int TPB = 256;
constexpr int ZPT = 16;          // doubles per thread
constexpr int INF = 0x7FFFFFFF;

__device__ double g_z[8 * NN];

// bytes of result = 0xFF where the source word (h0..h3) is negative
__device__ __forceinline__ unsigned sign_bytes(unsigned h0, unsigned h1,
                                               unsigned h2, unsigned h3) {
    unsigned p01, p23, r;
    asm("prmt.b32 %0, %1, %2, 0x00FB;" : "=r"(p01) : "r"(h0), "r"(h1));
    asm("prmt.b32 %0, %1, %2, 0x00FB;" : "=r"(p23) : "r"(h2), "r"(h3));
    asm("prmt.b32 %0, %1, %2, 0x5410;" : "=r"(r)   : "r"(p01), "r"(p23));
    return r;
}

// ---------------------------------------------------------------------------
// Kernel 1: z0 = W . x  (fp64). 8 rows per block; x staged transposed in smem.
// ---------------------------------------------------------------------------
constexpr int GROWS = 8;

__global__ void __launch_bounds__(256) gemv_init(const float* __restrict__ W,
                                                 const float* __restrict__ x,
                                                 int B)
{
    extern __shared__ float xs[];          // [NN][8], xs[c*8 + b]
    const int tid = threadIdx.x;

    if (B < 8) {
        for (int e = tid; e < NN * 8; e += 256) xs[e] = 0.f;
        __syncthreads();
    }
    for (int e = tid * 4; e < B * NN; e += 256 * 4) {
        const int bb = e / NN, c = e % NN;
        float4 v = *reinterpret_cast<const float4*>(x + e);
        xs[(c + 0) * 8 + bb] = v.x;
        xs[(c + 1) * 8 + bb] = v.y;
        xs[(c + 2) * 8 + bb] = v.z;
        xs[(c + 3) * 8 + bb] = v.w;
    }
    __syncthreads();

    __shared__ double red[8][8];
    const int wid = tid >> 5, lane = tid & 31;
    const int row0 = blockIdx.x * GROWS;

    for (int r = 0; r < GROWS; r++) {
        const float* wrow = W + (size_t)(row0 + r) * NN;
        double acc[8];
#pragma unroll
        for (int bb = 0; bb < 8; bb++) acc[bb] = 0.0;

#pragma unroll 4
        for (int j = 0; j < NN / 256; j++) {
            const int c = tid + j * 256;
            const double wd = (double)wrow[c];
            float4 xa = *reinterpret_cast<const float4*>(xs + c * 8);
            float4 xb = *reinterpret_cast<const float4*>(xs + c * 8 + 4);
            acc[0] = fma(wd, (double)xa.x, acc[0]);
            acc[1] = fma(wd, (double)xa.y, acc[1]);
            acc[2] = fma(wd, (double)xa.z, acc[2]);
            acc[3] = fma(wd, (double)xa.w, acc[3]);
            acc[4] = fma(wd, (double)xb.x, acc[4]);
            acc[5] = fma(wd, (double)xb.y, acc[5]);
            acc[6] = fma(wd, (double)xb.z, acc[6]);
            acc[7] = fma(wd, (double)xb.w, acc[7]);
        }
#pragma unroll
        for (int bb = 0; bb < 8; bb++) {
#pragma unroll
            for (int off = 16; off > 0; off >>= 1)
                acc[bb] += __shfl_down_sync(0xffffffffu, acc[bb], off);
        }
        if (lane == 0) {
#pragma unroll
            for (int bb = 0; bb < 8; bb++) red[wid][bb] = acc[bb];
        }
        __syncthreads();
        if (tid < 8) {
            double s = 0.0;
#pragma unroll
            for (int w2 = 0; w2 < 8; w2++) s += red[w2][tid];
            if (tid < B) g_z[tid * NN + row0 + r] = s;
        }
        __syncthreads();
    }
}

// ---------------------------------------------------------------------------
// Kernel 2: one block per sample.
// Key pack: bits[0]=nbit(z<0), [1:13]=i, [13:21]=tid. Min key = earliest step.
// ---------------------------------------------------------------------------
__global__ void __launch_bounds__(TPB) hopfield_seq(
    const float* __restrict__ W,
    const float* __restrict__ x,
    const int*   __restrict__ perms,
    float*       __restrict__ out,
    int iters)
{
    const int b    = blockIdx.x;
    const int tid  = threadIdx.x;
    const int lane = tid & 31;
    const int wid  = tid >> 5;
    const int base = tid * ZPT;

    __shared__ __align__(16) unsigned char sh_comb[NN];
    __shared__ __align__(16) int sh_slot[2][8];

    double z[ZPT];
    {
        const double* gz = g_z + (size_t)b * NN + base;
#pragma unroll
        for (int k = 0; k < ZPT; k++) z[k] = gz[k];
    }

    unsigned yexp[4];   // per-byte: 0x01 if y negative
    {
        const float4* x4 = reinterpret_cast<const float4*>(x + (size_t)b * NN + base);
        float4 xa = x4[0], xb = x4[1], xc = x4[2], xd = x4[3];
        yexp[0] = sign_bytes(__float_as_uint(xa.x), __float_as_uint(xa.y),
                             __float_as_uint(xa.z), __float_as_uint(xa.w)) & 0x01010101u;
        yexp[1] = sign_bytes(__float_as_uint(xb.x), __float_as_uint(xb.y),
                             __float_as_uint(xb.z), __float_as_uint(xb.w)) & 0x01010101u;
        yexp[2] = sign_bytes(__float_as_uint(xc.x), __float_as_uint(xc.y),
                             __float_as_uint(xc.z), __float_as_uint(xc.w)) & 0x01010101u;
        yexp[3] = sign_bytes(__float_as_uint(xd.x), __float_as_uint(xd.y),
                             __float_as_uint(xd.z), __float_as_uint(xd.w)) & 0x01010101u;

        uint4 cw;
        cw.x = (sign_bytes(__double2hiint(z[0]),  __double2hiint(z[1]),
                           __double2hiint(z[2]),  __double2hiint(z[3]))  & 0x02020202u) | yexp[0];
        cw.y = (sign_bytes(__double2hiint(z[4]),  __double2hiint(z[5]),
                           __double2hiint(z[6]),  __double2hiint(z[7]))  & 0x02020202u) | yexp[1];
        cw.z = (sign_bytes(__double2hiint(z[8]),  __double2hiint(z[9]),
                           __double2hiint(z[10]), __double2hiint(z[11])) & 0x02020202u) | yexp[2];
        cw.w = (sign_bytes(__double2hiint(z[12]), __double2hiint(z[13]),
                           __double2hiint(z[14]), __double2hiint(z[15])) & 0x02020202u) | yexp[3];
        *reinterpret_cast<uint4*>(sh_comb + base) = cw;
    }
    __syncthreads();

    const int  TOTAL = iters * NN;
    const int* pb    = perms + (size_t)b * TOTAL;

    int t = 0, parity = 0;
    while (t < TOTAL) {
        const int  step = t + tid;
        const bool in   = step < TOTAL;
        const int  i    = in ? __ldg(pb + step) : 0;
        int lastp = -1;

        for (;;) {
            // ---- candidate check against current signs ----
            int key = INF;
            if (in && tid > lastp) {
                const int cb = sh_comb[i];
                if (((cb >> 1) ^ cb) & 1)
                    key = (tid << 13) | (i << 1) | ((cb >> 1) & 1);
            }
            const unsigned ball = __ballot_sync(0xffffffffu, key != INF);
            if (ball) {
                if (lane == (int)(__ffs(ball) - 1)) sh_slot[parity][wid] = key;
            } else if (lane == 0) {
                sh_slot[parity][wid] = INF;
            }
            __syncthreads();                                   // barrier 1

            const int4 s0 = reinterpret_cast<const int4*>(sh_slot[parity])[0];
            const int4 s1 = reinterpret_cast<const int4*>(sh_slot[parity])[1];
            parity ^= 1;
            const int mk = min(min(min(s0.x, s0.y), min(s0.z, s0.w)),
                               min(min(s1.x, s1.y), min(s1.z, s1.w)));
            if (mk == INF) break;                              // stable: 1 barrier

            const int   first = mk >> 13;
            const int   fi    = (mk >> 1) & 0xFFF;
            const int   nb    = mk & 1;
            const float fd    = nb ? -2.0f : 2.0f;
            lastp = first;

            // ---- axpy loads (critical) ----
            const float4* w4 =
                reinterpret_cast<const float4*>(W + (size_t)fi * NN + base);
            const float4 wa = w4[0], wb_ = w4[1], wc = w4[2], wd_ = w4[3];

            // ---- prefetch runner-up candidate row (likely next winner) ----
            {
                int e0 = (s0.x == mk) ? INF : s0.x;
                int e1 = (s0.y == mk) ? INF : s0.y;
                int e2 = (s0.z == mk) ? INF : s0.z;
                int e3 = (s0.w == mk) ? INF : s0.w;
                int e4 = (s1.x == mk) ? INF : s1.x;
                int e5 = (s1.y == mk) ? INF : s1.y;
                int e6 = (s1.z == mk) ? INF : s1.z;
                int e7 = (s1.w == mk) ? INF : s1.w;
                const int mk2 = min(min(min(e0, e1), min(e2, e3)),
                                    min(min(e4, e5), min(e6, e7)));
                if (mk2 != INF) {
                    const char* p2 = reinterpret_cast<const char*>(
                        W + (size_t)((mk2 >> 1) & 0xFFF) * NN + base);
                    asm volatile("prefetch.global.L1 [%0];" :: "l"(p2));
                }
            }

            // owner patches its y bit before repacking
            if ((fi >> 4) == tid) {
                const int j = fi & 15;
                const unsigned m = 1u << (8 * (j & 3));
                if (nb) yexp[j >> 2] |= m; else yexp[j >> 2] &= ~m;
            }

            const float wv[ZPT] = {wa.x, wa.y, wa.z, wa.w,
                                   wb_.x, wb_.y, wb_.z, wb_.w,
                                   wc.x, wc.y, wc.z, wc.w,
                                   wd_.x, wd_.y, wd_.z, wd_.w};
#pragma unroll
            for (int k = 0; k < ZPT; k++)
                z[k] += (double)(fd * wv[k]);                 // fd*w exact in fp32

            uint4 cw;
            cw.x = (sign_bytes(__double2hiint(z[0]),  __double2hiint(z[1]),
                               __double2hiint(z[2]),  __double2hiint(z[3]))  & 0x02020202u) | yexp[0];
            cw.y = (sign_bytes(__double2hiint(z[4]),  __double2hiint(z[5]),
                               __double2hiint(z[6]),  __double2hiint(z[7]))  & 0x02020202u) | yexp[1];
            cw.z = (sign_bytes(__double2hiint(z[8]),  __double2hiint(z[9]),
                               __double2hiint(z[10]), __double2hiint(z[11])) & 0x02020202u) | yexp[2];
            cw.w = (sign_bytes(__double2hiint(z[12]), __double2hiint(z[13]),
                               __double2hiint(z[14]), __double2hiint(z[15])) & 0x02020202u) | yexp[3];
            *reinterpret_cast<uint4*>(sh_comb + base) = cw;
            __syncthreads();                                   // barrier 2
        }
        t += TPB;
    }

    // write y from register state
    float4 o[4];
#pragma unroll
    for (int w = 0; w < 4; w++) {
        float* ow = reinterpret_cast<float*>(&o[w]);
#pragma unroll
        for (int bp = 0; bp < 4; bp++)
            ow[bp] = ((yexp[w] >> (8 * bp)) & 1u) ? -1.0f : 1.0f;
    }
    float4* o4 = reinterpret_cast<float4*>(out + (size_t)b * NN + base);
#pragma unroll
    for (int w = 0; w < 4; w++) o4[w] = o[w];
}

// ---------------------------------------------------------------------------
extern "C" void kernel_launch(void* const* d_in, const int* in_sizes, int n_in,
                              void* d_out, int out_size)
{
    const float* x     = (const float*)d_in[0];
    const float* W     = (const float*)d_in[1];
    const int*   perms = (const int*)  d_in[2];
    float*       out   = (float*)d_out;

    const int B     = in_sizes[0] / NN;
    const int iters = in_sizes[2] / in_sizes[0];

    static bool attr_done = false;
    if (!attr_done) {   // idempotent host-side attribute, not a stream op
        cudaFuncSetAttribute(gemv_init,
                             cudaFuncAttributeMaxDynamicSharedMemorySize,
                             NN * 8 * (int)sizeof(float));
        attr_done = true;
    }

    gemv_init<<<NN / GROWS, 256, NN * 8 * sizeof(float)>>>(W, x, B);
    hopfield_seq<<<B, TPB>>>(W, x, perms, out, iters);
}

// round 4
// speedup vs baseline: 3.1816x; 1.8613x over previous
#include <cuda_runtime.h>

// HopfieldNetwork: B=8, N=4096, ITERS=10 asynchronous sweeps.
// Key change (R4): z kept as int64 fixed point (scale 2^-61) instead of fp64 —
// B300 fp64 rt is ~18.4 cyc/SM/warp-instr, which made the per-flip axpy
// (128 warp-DADDs) cost ~2350 cyc. Fixed-point update = FMUL + F2I + IADD3 pair,
// all rt-2 pipes. Updates fd*W are exact in fp32; conversion truncates below
// 2^-61, keeping z within ~1e-14 of exact (better than fp64 accumulation).

constexpr int NN  = 4096;
constexpr int TPB = 256;
constexpr int ZPT = 16;          // z elements per thread
constexpr int INF = 0x7FFFFFFF;

__device__ long long g_z[8 * NN];                      // z0, int64 scale 2^61
__device__ __align__(16) unsigned char g_xsign[NN];    // bit b = (x[b][c] < 0)

// bytes of result = 0xFF where the source word (h0..h3) is negative
__device__ __forceinline__ unsigned sign_bytes(unsigned h0, unsigned h1,
                                               unsigned h2, unsigned h3) {
    unsigned p01, p23, r;
    asm("prmt.b32 %0, %1, %2, 0x00FB;" : "=r"(p01) : "r"(h0), "r"(h1));
    asm("prmt.b32 %0, %1, %2, 0x00FB;" : "=r"(p23) : "r"(h2), "r"(h3));
    asm("prmt.b32 %0, %1, %2, 0x5410;" : "=r"(r)   : "r"(p01), "r"(p23));
    return r;
}

__device__ __forceinline__ unsigned hi32(long long v) {
    return (unsigned)(((unsigned long long)v) >> 32);
}

// ---------------------------------------------------------------------------
// Kernel 0: pack x signs into one byte per column.
// ---------------------------------------------------------------------------
__global__ void pack_x(const float* __restrict__ x, int B)
{
    const int c = blockIdx.x * 256 + threadIdx.x;
    unsigned v = 0;
#pragma unroll
    for (int b = 0; b < 8; b++)
        if (b < B && x[(size_t)b * NN + c] < 0.f) v |= 1u << b;
    g_xsign[c] = (unsigned char)v;
}

// ---------------------------------------------------------------------------
// Kernel 1: z0[b][row] = sum_c W[row][c] * x[b][c], int64 fixed point.
// One block per row. val = w * (+-2^61) is exact in fp32; cvt.rzi truncates.
// ---------------------------------------------------------------------------
__global__ void __launch_bounds__(256) gemv_init(const float* __restrict__ W,
                                                 int B)
{
    const int row  = blockIdx.x;
    const int tid  = threadIdx.x;
    const int base = tid * 16;
    const int lane = tid & 31, wid = tid >> 5;

    const uint4 sb4 = *reinterpret_cast<const uint4*>(g_xsign + base);
    const unsigned sb[4] = {sb4.x, sb4.y, sb4.z, sb4.w};

    const float4* w4 = reinterpret_cast<const float4*>(W + (size_t)row * NN + base);
    const float4 wa = w4[0], wb = w4[1], wc = w4[2], wd = w4[3];
    const float wv[16] = {wa.x, wa.y, wa.z, wa.w,  wb.x, wb.y, wb.z, wb.w,
                          wc.x, wc.y, wc.z, wc.w,  wd.x, wd.y, wd.z, wd.w};

    long long acc[8];
#pragma unroll
    for (int b = 0; b < 8; b++) acc[b] = 0ll;

#pragma unroll
    for (int k = 0; k < 16; k++) {
        const unsigned byte = (sb[k >> 2] >> (8 * (k & 3))) & 0xFFu;
        const float w = wv[k];
#pragma unroll
        for (int b = 0; b < 8; b++) {
            const float fs = ((byte >> b) & 1u) ? -0x1.0p61f : 0x1.0p61f;
            acc[b] += __float2ll_rz(w * fs);
        }
    }

#pragma unroll
    for (int b = 0; b < 8; b++) {
#pragma unroll
        for (int off = 16; off > 0; off >>= 1)
            acc[b] += __shfl_down_sync(0xffffffffu, acc[b], off);
    }
    __shared__ long long red[8][8];
    if (lane == 0) {
#pragma unroll
        for (int b = 0; b < 8; b++) red[wid][b] = acc[b];
    }
    __syncthreads();
    if (tid < 8) {
        long long s = 0ll;
#pragma unroll
        for (int w2 = 0; w2 < 8; w2++) s += red[w2][tid];
        if (tid < B) g_z[tid * NN + row] = s;
    }
}

// ---------------------------------------------------------------------------
// Kernel 2: one block per sample. sh_comb[i]: bit1 = (z[i]<0), bit0 = (y[i]<0).
// Flip iff bits differ. Window scan of 256 future perm steps; earliest flip
// via ballot + 8 warp slots + min; int64 axpy; PRMT sign repack; runner-up
// candidate W row prefetched to L1; next window's perm preloaded.
// Key pack: bits[0]=nb(z<0), [1:13]=i, [13:21]=tid.
// ---------------------------------------------------------------------------
__global__ void __launch_bounds__(TPB) hopfield_seq(
    const float* __restrict__ W,
    const float* __restrict__ x,
    const int*   __restrict__ perms,
    float*       __restrict__ out,
    int iters)
{
    const int b    = blockIdx.x;
    const int tid  = threadIdx.x;
    const int lane = tid & 31;
    const int wid  = tid >> 5;
    const int base = tid * ZPT;

    __shared__ __align__(16) unsigned char sh_comb[NN];
    __shared__ __align__(16) int sh_slot[2][8];

    long long z[ZPT];
    {
        const long long* gz = g_z + (size_t)b * NN + base;
#pragma unroll
        for (int k = 0; k < ZPT; k++) z[k] = gz[k];
    }

    unsigned yexp[4];   // per-byte: 0x01 if y negative
    {
        const float4* x4 = reinterpret_cast<const float4*>(x + (size_t)b * NN + base);
        float4 xa = x4[0], xb = x4[1], xc = x4[2], xd = x4[3];
        yexp[0] = sign_bytes(__float_as_uint(xa.x), __float_as_uint(xa.y),
                             __float_as_uint(xa.z), __float_as_uint(xa.w)) & 0x01010101u;
        yexp[1] = sign_bytes(__float_as_uint(xb.x), __float_as_uint(xb.y),
                             __float_as_uint(xb.z), __float_as_uint(xb.w)) & 0x01010101u;
        yexp[2] = sign_bytes(__float_as_uint(xc.x), __float_as_uint(xc.y),
                             __float_as_uint(xc.z), __float_as_uint(xc.w)) & 0x01010101u;
        yexp[3] = sign_bytes(__float_as_uint(xd.x), __float_as_uint(xd.y),
                             __float_as_uint(xd.z), __float_as_uint(xd.w)) & 0x01010101u;

        uint4 cw;
        cw.x = (sign_bytes(hi32(z[0]),  hi32(z[1]),  hi32(z[2]),  hi32(z[3]))  & 0x02020202u) | yexp[0];
        cw.y = (sign_bytes(hi32(z[4]),  hi32(z[5]),  hi32(z[6]),  hi32(z[7]))  & 0x02020202u) | yexp[1];
        cw.z = (sign_bytes(hi32(z[8]),  hi32(z[9]),  hi32(z[10]), hi32(z[11])) & 0x02020202u) | yexp[2];
        cw.w = (sign_bytes(hi32(z[12]), hi32(z[13]), hi32(z[14]), hi32(z[15])) & 0x02020202u) | yexp[3];
        *reinterpret_cast<uint4*>(sh_comb + base) = cw;
    }
    __syncthreads();

    const int  TOTAL = iters * NN;
    const int* pb    = perms + (size_t)b * TOTAL;

    int cur_i = (tid < TOTAL) ? __ldg(pb + tid) : 0;
    int parity = 0;

    for (int t = 0; t < TOTAL; t += TPB) {
        // preload next window's perm early (latency hidden behind this window)
        const int nstep = t + TPB + tid;
        const int nxt_i = (nstep < TOTAL) ? __ldg(pb + nstep) : 0;

        const int  step = t + tid;
        const bool in   = step < TOTAL;
        const int  i    = cur_i;
        int lastp = -1;

        for (;;) {
            // ---- candidate check against current signs ----
            int key = INF;
            if (in && tid > lastp) {
                const int cb = sh_comb[i];
                if (((cb >> 1) ^ cb) & 1)
                    key = (tid << 13) | (i << 1) | ((cb >> 1) & 1);
            }
            const unsigned ball = __ballot_sync(0xffffffffu, key != INF);
            if (ball) {
                if (lane == (int)(__ffs(ball) - 1)) sh_slot[parity][wid] = key;
            } else if (lane == 0) {
                sh_slot[parity][wid] = INF;
            }
            __syncthreads();                                   // barrier 1

            const int4 s0 = reinterpret_cast<const int4*>(sh_slot[parity])[0];
            const int4 s1 = reinterpret_cast<const int4*>(sh_slot[parity])[1];
            parity ^= 1;
            const int mk = min(min(min(s0.x, s0.y), min(s0.z, s0.w)),
                               min(min(s1.x, s1.y), min(s1.z, s1.w)));
            if (mk == INF) break;                              // stable window

            const int first = mk >> 13;
            const int fi    = (mk >> 1) & 0xFFF;
            const int nb    = mk & 1;
            lastp = first;

            // ---- axpy row loads (critical path) ----
            const float4* w4 =
                reinterpret_cast<const float4*>(W + (size_t)fi * NN + base);
            const float4 wa = w4[0], wb_ = w4[1], wc = w4[2], wd_ = w4[3];

            // ---- prefetch runner-up candidate row (likely next winner) ----
            {
                int e0 = (s0.x == mk) ? INF : s0.x;
                int e1 = (s0.y == mk) ? INF : s0.y;
                int e2 = (s0.z == mk) ? INF : s0.z;
                int e3 = (s0.w == mk) ? INF : s0.w;
                int e4 = (s1.x == mk) ? INF : s1.x;
                int e5 = (s1.y == mk) ? INF : s1.y;
                int e6 = (s1.z == mk) ? INF : s1.z;
                int e7 = (s1.w == mk) ? INF : s1.w;
                const int mk2 = min(min(min(e0, e1), min(e2, e3)),
                                    min(min(e4, e5), min(e6, e7)));
                if (mk2 != INF) {
                    const char* p2 = reinterpret_cast<const char*>(
                        W + (size_t)((mk2 >> 1) & 0xFFF) * NN + base);
                    asm volatile("prefetch.global.L1 [%0];" :: "l"(p2));
                }
            }

            // owner patches its y bit before repacking
            if ((fi >> 4) == tid) {
                const int j = fi & 15;
                const unsigned m = 1u << (8 * (j & 3));
                if (nb) yexp[j >> 2] |= m; else yexp[j >> 2] &= ~m;
            }

            // fd = +-2; combined with 2^61 scale: +-2^62 (exact fp32 scaling)
            const float fscale = nb ? -0x1.0p62f : 0x1.0p62f;
            const float wv[ZPT] = {wa.x, wa.y, wa.z, wa.w,
                                   wb_.x, wb_.y, wb_.z, wb_.w,
                                   wc.x, wc.y, wc.z, wc.w,
                                   wd_.x, wd_.y, wd_.z, wd_.w};
#pragma unroll
            for (int k = 0; k < ZPT; k++)
                z[k] += __float2ll_rz(wv[k] * fscale);

            uint4 cw;
            cw.x = (sign_bytes(hi32(z[0]),  hi32(z[1]),  hi32(z[2]),  hi32(z[3]))  & 0x02020202u) | yexp[0];
            cw.y = (sign_bytes(hi32(z[4]),  hi32(z[5]),  hi32(z[6]),  hi32(z[7]))  & 0x02020202u) | yexp[1];
            cw.z = (sign_bytes(hi32(z[8]),  hi32(z[9]),  hi32(z[10]), hi32(z[11])) & 0x02020202u) | yexp[2];
            cw.w = (sign_bytes(hi32(z[12]), hi32(z[13]), hi32(z[14]), hi32(z[15])) & 0x02020202u) | yexp[3];
            *reinterpret_cast<uint4*>(sh_comb + base) = cw;
            __syncthreads();                                   // barrier 2
        }
        cur_i = nxt_i;
    }

    // write y from register state
    float4 o[4];
#pragma unroll
    for (int w = 0; w < 4; w++) {
        float* ow = reinterpret_cast<float*>(&o[w]);
#pragma unroll
        for (int bp = 0; bp < 4; bp++)
            ow[bp] = ((yexp[w] >> (8 * bp)) & 1u) ? -1.0f : 1.0f;
    }
    float4* o4 = reinterpret_cast<float4*>(out + (size_t)b * NN + base);
#pragma unroll
    for (int w = 0; w < 4; w++) o4[w] = o[w];
}

// ---------------------------------------------------------------------------
extern "C" void kernel_launch(void* const* d_in, const int* in_sizes, int n_in,
                              void* d_out, int out_size)
{
    const float* x     = (const float*)d_in[0];
    const float* W     = (const float*)d_in[1];
    const int*   perms = (const int*)  d_in[2];
    float*       out   = (float*)d_out;

    const int B     = in_sizes[0] / NN;
    const int iters = in_sizes[2] / in_sizes[0];

    pack_x<<<NN / 256, 256>>>(x, B);
    gemv_init<<<NN, 256>>>(W, B);
    hopfield_seq<<<B, TPB>>>(W, x, perms, out, iters);
}